// round 6
// baseline (speedup 1.0000x reference)
#include <cuda_runtime.h>
#include <cstdint>

// DepthwiseStencil3D: x (1,16,128,128,128) fp32 -> out flat channels ch = c*6+k.
// Taps (k): 0 -> w+1, 1 -> w-1, 2 -> h+1, 3 -> h-1, 4 -> d+1, 5 -> d-1.
//
// TMA-store variant: each CTA (256 thr) computes a 16-row x 128-wide tile of one
// (c, d) slice, stages the 6 tap outputs in SMEM (6 x 8KB), then emits them as
// six 8KB cp.async.bulk shared->global bursts (evict-first L2 policy). Loads
// stay 256-bit LDG; w-edge scalars via warp shuffle.

#define C_ 16
#define D_ 128
#define H_ 128
#define W_ 128
#define HW_ (H_ * W_)          // 16384
#define DHW_ (D_ * HW_)        // 2097152

#define HB_ 16                 // h-rows per CTA tile
#define TILE_ELEMS (HB_ * W_)  // 2048 floats
#define TILE_BYTES (TILE_ELEMS * 4)  // 8192

struct V8 { uint32_t r[8]; };

__device__ __forceinline__ V8 ldg_v8(const float* p) {
    V8 v;
    asm volatile("ld.global.v8.b32 {%0,%1,%2,%3,%4,%5,%6,%7}, [%8];"
                 : "=r"(v.r[0]), "=r"(v.r[1]), "=r"(v.r[2]), "=r"(v.r[3]),
                   "=r"(v.r[4]), "=r"(v.r[5]), "=r"(v.r[6]), "=r"(v.r[7])
                 : "l"(p));
    return v;
}

__device__ __forceinline__ void sts_v8(float* dst, const V8& v) {
    uint4* d = reinterpret_cast<uint4*>(dst);
    d[0] = make_uint4(v.r[0], v.r[1], v.r[2], v.r[3]);
    d[1] = make_uint4(v.r[4], v.r[5], v.r[6], v.r[7]);
}

__device__ __forceinline__ uint32_t smem_u32(const void* p) {
    uint32_t a;
    asm("{ .reg .u64 t; cvta.to.shared.u64 t, %1; cvt.u32.u64 %0, t; }"
        : "=r"(a) : "l"(p));
    return a;
}

__global__ void __launch_bounds__(256) stencil6_kernel(
    const float* __restrict__ x, float* __restrict__ out)
{
    __shared__ float sbuf[6][TILE_ELEMS];   // 48 KB

    int tid = threadIdx.x;
    int w8  = tid & 15;            // 8-float chunk along W (W/8 = 16)
    int hr  = tid >> 4;            // 0..15 row within tile
    int bid = blockIdx.x;
    int hb  = bid & 7;             // 8 h-blocks of 16 rows
    int d   = (bid >> 3) & 127;
    int c   = bid >> 10;           // 0..15

    int h       = hb * HB_ + hr;
    int spatial = d * HW_ + h * W_ + (w8 << 3);
    int base    = c * DHW_ + spatial;

    V8 zero;
#pragma unroll
    for (int i = 0; i < 8; i++) zero.r[i] = 0u;

    // Front-batched 256-bit loads (zero outside the volume == zero padding).
    V8 v   = ldg_v8(x + base);
    V8 vhp = (h < H_ - 1) ? ldg_v8(x + base + W_)  : zero;
    V8 vhm = (h > 0)      ? ldg_v8(x + base - W_)  : zero;
    V8 vdp = (d < D_ - 1) ? ldg_v8(x + base + HW_) : zero;
    V8 vdm = (d > 0)      ? ldg_v8(x + base - HW_) : zero;

    // w-edge scalars via intra-warp shuffle (lane +/-1 = adjacent chunk; row
    // seams are masked to zero by the padding predicates).
    unsigned full = 0xffffffffu;
    uint32_t xl = __shfl_up_sync(full, v.r[7], 1);
    uint32_t xr = __shfl_down_sync(full, v.r[0], 1);
    if (w8 == 0)  xl = 0u;
    if (w8 == 15) xr = 0u;

    V8 k0, k1;
#pragma unroll
    for (int i = 0; i < 7; i++) k0.r[i] = v.r[i + 1];
    k0.r[7] = xr;
    k1.r[0] = xl;
#pragma unroll
    for (int i = 1; i < 8; i++) k1.r[i] = v.r[i - 1];

    // Stage all 6 taps in SMEM (row-major tile, matches global layout).
    int so = hr * W_ + (w8 << 3);
    sts_v8(&sbuf[0][so], k0);
    sts_v8(&sbuf[1][so], k1);
    sts_v8(&sbuf[2][so], vhp);
    sts_v8(&sbuf[3][so], vhm);
    sts_v8(&sbuf[4][so], vdp);
    sts_v8(&sbuf[5][so], vdm);

    __syncthreads();

    // One thread per tap issues an 8KB bulk shared->global burst.
    if (tid < 6) {
        asm volatile("fence.proxy.async.shared::cta;" ::: "memory");
        uint32_t saddr = smem_u32(&sbuf[tid][0]);
        float* gdst = out + (c * 6 + tid) * DHW_ + d * HW_ + hb * TILE_ELEMS;
        asm volatile(
            "{ .reg .b64 pol;\n"
            "  createpolicy.fractional.L2::evict_first.b64 pol, 1.0;\n"
            "  cp.async.bulk.global.shared::cta.bulk_group.L2::cache_hint"
            "  [%0], [%1], %2, pol; }\n"
            :: "l"(gdst), "r"(saddr), "n"(TILE_BYTES) : "memory");
        asm volatile("cp.async.bulk.commit_group;" ::: "memory");
        asm volatile("cp.async.bulk.wait_group 0;" ::: "memory");
    }
}

extern "C" void kernel_launch(void* const* d_in, const int* in_sizes, int n_in,
                              void* d_out, int out_size)
{
    const float* x = (const float*)d_in[0];
    float* out = (float*)d_out;

    // blocks enumerate (c, d, hb): 16 * 128 * 8 = 16384
    stencil6_kernel<<<16384, 256>>>(x, out);
}

// round 7
// speedup vs baseline: 1.0634x; 1.0634x over previous
#include <cuda_runtime.h>
#include <cstdint>

// DepthwiseStencil3D, output-linear variant.
// out flat channel ch = c*6+k is x[c] shifted by tap k, zero-padded.
// Taps: 0 -> w+1, 1 -> w-1, 2 -> h+1, 3 -> h-1, 4 -> d+1, 5 -> d-1.
//
// Each CTA owns one contiguous 8192-element (32 KB) region of ONE output
// channel: the global write pattern is a linear sweep of the output buffer.
// Per chunk: one predicated 256-bit load + one streaming 256-bit store.
// Tap kind is uniform per CTA. 4 chunks/thread for MLP.

#define C_ 16
#define D_ 128
#define H_ 128
#define W_ 128
#define HW_ (H_ * W_)          // 16384
#define DHW_ (D_ * HW_)        // 2097152

struct V8 { uint32_t r[8]; };

__device__ __forceinline__ V8 ldg_v8(const float* p) {
    V8 v;
    asm volatile("ld.global.v8.b32 {%0,%1,%2,%3,%4,%5,%6,%7}, [%8];"
                 : "=r"(v.r[0]), "=r"(v.r[1]), "=r"(v.r[2]), "=r"(v.r[3]),
                   "=r"(v.r[4]), "=r"(v.r[5]), "=r"(v.r[6]), "=r"(v.r[7])
                 : "l"(p));
    return v;
}

__device__ __forceinline__ void stg_cs_v8(float* p, const V8& v) {
    asm volatile("st.global.cs.v8.b32 [%0], {%1,%2,%3,%4,%5,%6,%7,%8};"
                 :: "l"(p),
                    "r"(v.r[0]), "r"(v.r[1]), "r"(v.r[2]), "r"(v.r[3]),
                    "r"(v.r[4]), "r"(v.r[5]), "r"(v.r[6]), "r"(v.r[7])
                 : "memory");
}

__global__ void __launch_bounds__(256) stencil6_kernel(
    const float* __restrict__ x, float* __restrict__ out)
{
    int t   = threadIdx.x;
    int bid = blockIdx.x;

    int ch  = bid >> 8;           // output channel 0..95
    int reg = bid & 255;          // 8192-element region within channel
    int c   = ch / 6;
    int k   = ch - 6 * c;         // tap kind, uniform per CTA

    const float* __restrict__ xc = x + c * DHW_;
    float* __restrict__ ob = out + ch * DHW_;

    int regbase = reg << 13;      // * 8192
    int off0 = regbase + (t << 3);

    V8 zero;
#pragma unroll
    for (int i = 0; i < 8; i++) zero.r[i] = 0u;

    V8 res[4];

    if (k < 2) {
        // w-shift taps: aligned load + lane shuffle for the edge scalar.
        unsigned full = 0xffffffffu;
        int w8 = t & 15;          // 8-float chunk index within the W row
        V8 v[4];
#pragma unroll
        for (int i = 0; i < 4; i++) v[i] = ldg_v8(xc + off0 + (i << 11));

        if (k == 0) {             // w+1
#pragma unroll
            for (int i = 0; i < 4; i++) {
                uint32_t xr = __shfl_down_sync(full, v[i].r[0], 1);
                if (w8 == 15) xr = 0u;
#pragma unroll
                for (int j = 0; j < 7; j++) res[i].r[j] = v[i].r[j + 1];
                res[i].r[7] = xr;
            }
        } else {                  // w-1
#pragma unroll
            for (int i = 0; i < 4; i++) {
                uint32_t xl = __shfl_up_sync(full, v[i].r[7], 1);
                if (w8 == 0) xl = 0u;
                res[i].r[0] = xl;
#pragma unroll
                for (int j = 1; j < 8; j++) res[i].r[j] = v[i].r[j - 1];
            }
        }
    } else {
        // h/d-shift taps: pure shifted copies with zero padding at the edge.
        int delta = (k == 2) ?  W_  :
                    (k == 3) ? -W_  :
                    (k == 4) ?  HW_ : -HW_;
#pragma unroll
        for (int i = 0; i < 4; i++) {
            int o = off0 + (i << 11);
            bool ok;
            if      (k == 2) ok = ((o >> 7) & 127) < H_ - 1;  // h < 127
            else if (k == 3) ok = ((o >> 7) & 127) > 0;       // h > 0
            else if (k == 4) ok = (o >> 14) < D_ - 1;         // d < 127
            else             ok = (o >> 14) > 0;              // d > 0
            res[i] = ok ? ldg_v8(xc + o + delta) : zero;
        }
    }

#pragma unroll
    for (int i = 0; i < 4; i++) stg_cs_v8(ob + off0 + (i << 11), res[i]);
}

extern "C" void kernel_launch(void* const* d_in, const int* in_sizes, int n_in,
                              void* d_out, int out_size)
{
    const float* x = (const float*)d_in[0];
    float* out = (float*)d_out;

    // 96 channels * 256 regions = 24576 CTAs; each writes 32 KB contiguous.
    stencil6_kernel<<<24576, 256>>>(x, out);
}